// round 5
// baseline (speedup 1.0000x reference)
#include <cuda_runtime.h>
#include <cuda_bf16.h>
#include <cmath>

#define BATCH 32
#define NPTS  1024
#define FDIM  7
#define HID   256
#define MLP_H 64
#define OUTD  8

// ---------------- scratch (device globals) ----------------
__device__ unsigned g_adjw[BATCH*32*NPTS];        // adjacency bitmask, 4 MB
__device__ float4   g_ppc[BATCH*NPTS];            // (pp0, pp1, cc, 0)
__device__ float    g_maxpart[BATCH*4];
__device__ float    g_glo[BATCH*2];               // avg_speed, density
__device__ float    g_upart[BATCH*8*HID];
__device__ float    g_mlpPart[BATCH*7*MLP_H];
__device__ float    g_E[OUTD*HID];                // folded GCN head: Wp_gcn@Wfc@W2
__device__ float    g_c0[OUTD];                   // folded GCN bias contribution

// ---------------- KA: fused adjacency(symmetric tiles) + MLP layer-1 + head fold ----------------
// blocks [0,128): adjacency, b = bx>>2; 64 warps/batch cover 528 upper-tri tiles
// blocks [128,184): mlp1 partials (7 slices x 8 batch-groups)
// blocks [184,192): GCN-head fold, one block per output row o
__global__ void __launch_bounds__(512)
kA(const float* __restrict__ x, const float* __restrict__ Wm0,
   const float* __restrict__ Wfc, const float* __restrict__ W2,
   const float* __restrict__ b2, const float* __restrict__ bfc,
   const float* __restrict__ Wp, float C) {
    const int tid = threadIdx.x;
    const int lane = tid & 31, w = tid >> 5;      // 16 warps
    __shared__ float4 S4[NPTS];                   // 16KB, role-shared
    __shared__ float wred[16];

    const int bx = blockIdx.x;
    if (bx < 128) {
        // ---------------- adjacency: upper-triangle tiles + bit-transpose mirror ----------------
        const int b = bx >> 2;
        for (int i = tid; i < NPTS; i += 512) {
            const float* xp = x + (size_t)(b*NPTS + i)*FDIM;
            const float p0 = xp[1], p1 = xp[2];
            S4[i] = make_float4(p0, p1, fmaf(p0, p0, p1*p1), 0.f);
        }
        __syncthreads();

        const int ww = (bx & 3)*16 + w;           // warp id within batch, 0..63
        int L    = (ww*528) >> 6;
        const int Lend = ((ww + 1)*528) >> 6;

        // decode L -> (jb, kb), kb >= jb
        int jb = 0, rem = L;
        while (rem >= 32 - jb) { rem -= 32 - jb; jb++; }
        int kb = jb + rem;

        unsigned* __restrict__ aw = &g_adjw[(size_t)b*32*NPTS];
        float dmax = -1e30f;

        for (; L < Lend; L++) {
            const float4 pj = S4[jb*32 + lane];
            const float m2p0 = -2.0f*pj.x, m2p1 = -2.0f*pj.y;
            const float cj = C - pj.z;
            const float4* Pk = &S4[kb*32];
            unsigned myw = 0;
            float em = -1e30f;
            #pragma unroll 4
            for (int t = 0; t < 32; t++) {
                const float4 pk = Pk[t];                       // broadcast LDS.128
                const float e = fmaf(m2p0, pk.x, fmaf(m2p1, pk.y, pk.z));
                em = fmaxf(em, e);
                const unsigned bal = __ballot_sync(0xffffffffu, e < cj);
                if (lane == t) myw = bal;                      // lane t: row kb*32+t, bits j
            }
            dmax = fmaxf(dmax, em + pj.z);
            aw[(jb << 10) + kb*32 + lane] = myw;               // colblock jb, rows kb*32+..

            if (kb != jb) {
                // warp 32x32 bit-matrix transpose: B[r][c] = T[c][r]
                unsigned xw = myw;
                #pragma unroll
                for (int i = 4; i >= 0; i--) {
                    const int s = 1 << i;
                    const unsigned msk = (i == 4) ? 0x0000FFFFu :
                                         (i == 3) ? 0x00FF00FFu :
                                         (i == 2) ? 0x0F0F0F0Fu :
                                         (i == 1) ? 0x33333333u : 0x55555555u;
                    const unsigned y = __shfl_xor_sync(0xffffffffu, xw, s);
                    xw = (lane & s) ? ((xw & ~msk) | ((y >> s) & msk))
                                    : ((xw & msk) | ((y & msk) << s));
                }
                aw[(kb << 10) + jb*32 + lane] = xw;            // colblock kb, rows jb*32+..
            }
            if (++kb == 32) { jb++; kb = jb; }
        }

        #pragma unroll
        for (int s = 16; s > 0; s >>= 1)
            dmax = fmaxf(dmax, __shfl_xor_sync(0xffffffffu, dmax, s));
        if (lane == 0) wred[w] = dmax;
        __syncthreads();
        if (tid == 0) {
            float mx = wred[0];
            #pragma unroll
            for (int i = 1; i < 16; i++) mx = fmaxf(mx, wred[i]);
            g_maxpart[b*4 + (bx & 3)] = mx;
        }
    } else if (bx < 184) {
        // ---------------- mlp1 partials ----------------
        const int mi = bx - 128;
        const int sl = mi % 7, b0 = (mi / 7)*4;
        float4 (*sx)[256] = reinterpret_cast<float4(*)[256]>(S4);
        for (int q = tid; q < 1024; q += 512) {
            const int bb = q >> 8, e = q & 255;
            sx[bb][e] = ((const float4*)(x + (size_t)(b0 + bb)*(NPTS*FDIM) + sl*1024))[e];
        }
        __syncthreads();

        const int h0 = w*4;
        float acc[4][4];
        #pragma unroll
        for (int r = 0; r < 4; r++)
            #pragma unroll
            for (int bb = 0; bb < 4; bb++) acc[r][bb] = 0.f;

        #pragma unroll
        for (int it = 0; it < 8; it++) {
            const int e = it*32 + lane;
            const float4 x0 = sx[0][e], x1 = sx[1][e], x2 = sx[2][e], x3 = sx[3][e];
            #pragma unroll
            for (int r = 0; r < 4; r++) {
                const float4 wv = ((const float4*)(Wm0 + (size_t)(h0 + r)*(NPTS*FDIM) + sl*1024))[e];
                acc[r][0] = fmaf(wv.x, x0.x, acc[r][0]); acc[r][0] = fmaf(wv.y, x0.y, acc[r][0]);
                acc[r][0] = fmaf(wv.z, x0.z, acc[r][0]); acc[r][0] = fmaf(wv.w, x0.w, acc[r][0]);
                acc[r][1] = fmaf(wv.x, x1.x, acc[r][1]); acc[r][1] = fmaf(wv.y, x1.y, acc[r][1]);
                acc[r][1] = fmaf(wv.z, x1.z, acc[r][1]); acc[r][1] = fmaf(wv.w, x1.w, acc[r][1]);
                acc[r][2] = fmaf(wv.x, x2.x, acc[r][2]); acc[r][2] = fmaf(wv.y, x2.y, acc[r][2]);
                acc[r][2] = fmaf(wv.z, x2.z, acc[r][2]); acc[r][2] = fmaf(wv.w, x2.w, acc[r][2]);
                acc[r][3] = fmaf(wv.x, x3.x, acc[r][3]); acc[r][3] = fmaf(wv.y, x3.y, acc[r][3]);
                acc[r][3] = fmaf(wv.z, x3.z, acc[r][3]); acc[r][3] = fmaf(wv.w, x3.w, acc[r][3]);
            }
        }
        #pragma unroll
        for (int r = 0; r < 4; r++)
            #pragma unroll
            for (int bb = 0; bb < 4; bb++) {
                float v = acc[r][bb];
                #pragma unroll
                for (int s = 16; s > 0; s >>= 1) v += __shfl_xor_sync(0xffffffffu, v, s);
                if (lane == 0) g_mlpPart[((b0 + bb)*7 + sl)*MLP_H + h0 + r] = v;
            }
    } else {
        // ---------------- GCN-head fold: E[o,:] = (Wp_gcn[o,:]@Wfc)@W2 ----------------
        const int o = bx - 184;
        const float* wp = Wp + (size_t)o*(MLP_H + HID + OUTD) + MLP_H;   // Wp_gcn row o
        float* sA = (float*)S4;

        if (tid < HID) {
            float a = 0.f;
            #pragma unroll 8
            for (int k = 0; k < HID; k++)
                a = fmaf(wp[k], Wfc[(size_t)k*HID + tid], a);
            sA[tid] = a;
        }
        __syncthreads();

        float v = (tid < HID) ? fmaf(sA[tid], b2[tid], wp[tid]*bfc[tid]) : 0.f;
        #pragma unroll
        for (int s = 16; s > 0; s >>= 1) v += __shfl_xor_sync(0xffffffffu, v, s);
        if (lane == 0) wred[w] = v;
        __syncthreads();
        if (tid == 0) {
            float c = 0.f;
            #pragma unroll
            for (int i = 0; i < 8; i++) c += wred[i];
            g_c0[o] = c;
        }

        if (tid < HID) {
            float e = 0.f;
            #pragma unroll 8
            for (int k = 0; k < HID; k++)
                e = fmaf(sA[k], W2[(size_t)k*HID + tid], e);
            g_E[o*HID + tid] = e;
        }
    }
}

// ---------------- KB: degrees + sparse gather + global scalars ----------------
__global__ void __launch_bounds__(1024)
k_gup(const float* __restrict__ x) {
    cudaGridDependencySynchronize();
    const int b = blockIdx.x;
    const int j = threadIdx.x;
    const int lane = j & 31, wid = j >> 5;

    __shared__ float sp0[NPTS], sp1[NPTS], sdv[NPTS];
    __shared__ float red[32];

    const float* xp = x + (size_t)(b*NPTS + j)*FDIM;
    const float p0 = xp[1], p1 = xp[2];
    const float x3 = xp[3], x4 = xp[4];
    sp0[j] = p0; sp1[j] = p1;
    float sp = sqrtf(fmaf(x3, x3, x4*x4));

    unsigned wr[32]; int cnt = 0;
    #pragma unroll
    for (int cb = 0; cb < 32; cb++) {
        wr[cb] = g_adjw[((size_t)b*32 + cb)*NPTS + j];
        cnt += __popc(wr[cb]);
    }
    const float dinv = 1.0f / sqrtf((float)cnt);
    sdv[j] = dinv;

    #pragma unroll
    for (int s = 16; s > 0; s >>= 1) sp += __shfl_xor_sync(0xffffffffu, sp, s);
    if (lane == 0) red[wid] = sp;
    __syncthreads();

    float s0 = 0.f, s1 = 0.f, t = 0.f;
    for (int cb = 0; cb < 32; cb++) {
        unsigned m = wr[cb];
        const int base = cb*32;
        while (m) {
            const int i = __ffs(m) - 1;
            m &= m - 1;
            const int k = base + i;
            const float d = sdv[k];
            s0 = fmaf(d, sp0[k], s0);
            s1 = fmaf(d, sp1[k], s1);
            t += d;
        }
    }
    g_ppc[b*NPTS + j] = make_float4(dinv*s0, dinv*s1, dinv*t, 0.f);

    if (wid == 0) {
        float v = red[lane];
        #pragma unroll
        for (int s = 16; s > 0; s >>= 1) v += __shfl_xor_sync(0xffffffffu, v, s);
        if (lane == 0) {
            float mx = fmaxf(fmaxf(g_maxpart[b*4+0], g_maxpart[b*4+1]),
                             fmaxf(g_maxpart[b*4+2], g_maxpart[b*4+3]));
            g_glo[b*2 + 0] = v * (1.0f/1024.0f);
            g_glo[b*2 + 1] = 1.0f / sqrtf(mx);
        }
    }
}

// ---------------- KC: u partials — 128-chunks, 4 independent streams ----------------
__global__ void __launch_bounds__(256)
k_upart(const float* __restrict__ W1, const float* __restrict__ b1) {
    const int chunk = blockIdx.x, b = blockIdx.y;
    const int d = threadIdx.x;

    const float w0 = W1[2*d], w1 = W1[2*d + 1], bd = b1[d];

    cudaGridDependencySynchronize();
    __shared__ float4 S[128];
    if (d < 128) S[d] = g_ppc[b*NPTS + chunk*128 + d];
    __syncthreads();

    float a0 = 0.f, a1 = 0.f, a2 = 0.f, a3 = 0.f;
    #pragma unroll 8
    for (int i = 0; i < 32; i++) {
        const float4 v0 = S[i], v1 = S[32 + i], v2 = S[64 + i], v3 = S[96 + i];
        float t0 = fmaf(w1, v0.y, fmaf(w0, v0.x, bd)); t0 = fmaxf(t0, 0.f);
        float t1 = fmaf(w1, v1.y, fmaf(w0, v1.x, bd)); t1 = fmaxf(t1, 0.f);
        float t2 = fmaf(w1, v2.y, fmaf(w0, v2.x, bd)); t2 = fmaxf(t2, 0.f);
        float t3 = fmaf(w1, v3.y, fmaf(w0, v3.x, bd)); t3 = fmaxf(t3, 0.f);
        a0 = fmaf(v0.z, t0, a0);
        a1 = fmaf(v1.z, t1, a1);
        a2 = fmaf(v2.z, t2, a2);
        a3 = fmaf(v3.z, t3, a3);
    }
    g_upart[(b*8 + chunk)*HID + d] = (a0 + a1) + (a2 + a3);
}

// ---------------- KD: folded head — m, mlp finish, glo, output ----------------
__global__ void __launch_bounds__(256)
kD(const float* __restrict__ Wg, const float* __restrict__ bgv,
   const float* __restrict__ Wm1, const float* __restrict__ bm1,
   const float* __restrict__ bm0,
   const float* __restrict__ Wp, const float* __restrict__ bp,
   float* __restrict__ out) {
    cudaGridDependencySynchronize();
    const int b = blockIdx.x;
    const int tid = threadIdx.x;
    const int lane = tid & 31, w = tid >> 5;

    __shared__ float sm[HID];
    __shared__ float m0[MLP_H], m1[MLP_H];
    __shared__ float glo8[OUTD];

    float u = 0.f;
    #pragma unroll
    for (int c = 0; c < 8; c++) u += g_upart[(b*8 + c)*HID + tid];
    sm[tid] = u * (1.0f/1024.0f);

    if (tid < OUTD) {
        const float gl0 = g_glo[b*2], gl1 = g_glo[b*2 + 1];
        const float ge = fmaf(Wg[2*tid], gl0, fmaf(Wg[2*tid + 1], gl1, bgv[tid]));
        glo8[tid] = fmaxf(ge, 0.f);
    }
    if (tid < MLP_H) {
        float a = bm0[tid];
        #pragma unroll
        for (int s = 0; s < 7; s++) a += g_mlpPart[(b*7 + s)*MLP_H + tid];
        m0[tid] = fmaxf(a, 0.f);
    }
    __syncthreads();

    // mlp layer 2: 64 outputs x 4 threads
    {
        const int od = tid >> 2, q = tid & 3;
        const float4* wr4 = (const float4*)(Wm1 + (size_t)od*MLP_H + q*16);
        const float4* mm4 = (const float4*)(m0 + q*16);
        float p = 0.f;
        #pragma unroll
        for (int e = 0; e < 4; e++) {
            const float4 wv = wr4[e], mv = mm4[e];
            p = fmaf(wv.x, mv.x, p); p = fmaf(wv.y, mv.y, p);
            p = fmaf(wv.z, mv.z, p); p = fmaf(wv.w, mv.w, p);
        }
        p += __shfl_xor_sync(0xffffffffu, p, 1);
        p += __shfl_xor_sync(0xffffffffu, p, 2);
        if (q == 0) m1[od] = fmaxf(p + bm1[od], 0.f);
    }
    __syncthreads();

    // output: warp o computes out[b, o]
    {
        const int o = w;
        const float* Eo = g_E + o*HID;
        const float* wp = Wp + (size_t)o*(MLP_H + HID + OUTD);
        float p = 0.f;
        #pragma unroll
        for (int c = 0; c < 8; c++)
            p = fmaf(Eo[c*32 + lane], sm[c*32 + lane], p);
        p = fmaf(wp[lane],      m1[lane],      p);
        p = fmaf(wp[32 + lane], m1[32 + lane], p);
        if (lane < OUTD) p = fmaf(wp[320 + lane], glo8[lane], p);
        #pragma unroll
        for (int s = 16; s > 0; s >>= 1) p += __shfl_xor_sync(0xffffffffu, p, s);
        if (lane == 0) out[b*OUTD + o] = p + bp[o] + g_c0[o];
    }
}

// ---------------- launch (PDL chain) ----------------
extern "C" void kernel_launch(void* const* d_in, const int* in_sizes, int n_in,
                              void* d_out, int out_size) {
    (void)in_sizes; (void)n_in; (void)out_size;
    const float* x   = (const float*)d_in[0];
    const float* W1  = (const float*)d_in[1];
    const float* b1  = (const float*)d_in[2];
    const float* W2  = (const float*)d_in[3];
    const float* b2  = (const float*)d_in[4];
    const float* Wfc = (const float*)d_in[5];
    const float* bfc = (const float*)d_in[6];
    const float* Wg  = (const float*)d_in[7];
    const float* bg  = (const float*)d_in[8];
    const float* Wm0 = (const float*)d_in[9];
    const float* bm0 = (const float*)d_in[10];
    const float* Wm1 = (const float*)d_in[11];
    const float* bm1 = (const float*)d_in[12];
    const float* Wp  = (const float*)d_in[13];
    const float* bp  = (const float*)d_in[14];
    float* out = (float*)d_out;

    // smallest C with sqrtf(C) >= 0.3f  =>  (d2 < C) <=> (sqrtf(d2) < 0.3f)
    float C = 0.09f;
    while (sqrtf(C) >= 0.3f) C = nextafterf(C, 0.0f);
    while (sqrtf(C) <  0.3f) C = nextafterf(C, 1.0f);

    kA<<<192, 512>>>(x, Wm0, Wfc, W2, b2, bfc, Wp, C);

    cudaLaunchAttribute attr[1];
    attr[0].id = cudaLaunchAttributeProgrammaticStreamSerialization;
    attr[0].val.programmaticStreamSerializationAllowed = 1;

    {
        cudaLaunchConfig_t cfg = {};
        cfg.gridDim = dim3(BATCH); cfg.blockDim = dim3(1024);
        cfg.attrs = attr; cfg.numAttrs = 1; cfg.stream = 0;
        cudaLaunchKernelEx(&cfg, k_gup, x);
    }
    {
        cudaLaunchConfig_t cfg = {};
        cfg.gridDim = dim3(8, BATCH); cfg.blockDim = dim3(256);
        cfg.attrs = attr; cfg.numAttrs = 1; cfg.stream = 0;
        cudaLaunchKernelEx(&cfg, k_upart, W1, b1);
    }
    {
        cudaLaunchConfig_t cfg = {};
        cfg.gridDim = dim3(BATCH); cfg.blockDim = dim3(256);
        cfg.attrs = attr; cfg.numAttrs = 1; cfg.stream = 0;
        cudaLaunchKernelEx(&cfg, kD, Wg, bg, Wm1, bm1, bm0, Wp, bp, out);
    }
}

// round 6
// speedup vs baseline: 1.1071x; 1.1071x over previous
#include <cuda_runtime.h>
#include <cuda_bf16.h>
#include <cmath>

#define BATCH 32
#define NPTS  1024
#define FDIM  7
#define HID   256
#define MLP_H 64
#define OUTD  8

// ---------------- scratch (device globals) ----------------
__device__ unsigned g_adjw[BATCH*32*NPTS];        // adjacency bitmask, 4 MB
__device__ float    g_maxpart[BATCH*4];
__device__ float    g_mlpPart[BATCH*7*MLP_H];
__device__ float    g_E[OUTD*HID];                // folded GCN head: Wp_gcn@Wfc@W2
__device__ float    g_c0[OUTD];                   // folded GCN bias contribution

// ---------------- KA: fused adjacency + MLP layer-1 + GCN-head fold (round-4 layout) ----------------
// blocks [0,128): adjacency (b = bx>>2, j-group = bx&3)
// blocks [128,184): mlp1 partials (7 slices x 8 batch-groups)
// blocks [184,192): GCN-head fold, one block per output row o
__global__ void __launch_bounds__(512)
kA(const float* __restrict__ x, const float* __restrict__ Wm0,
   const float* __restrict__ Wfc, const float* __restrict__ W2,
   const float* __restrict__ b2, const float* __restrict__ bfc,
   const float* __restrict__ Wp, float C) {
    const int tid = threadIdx.x;
    const int lane = tid & 31, w = tid >> 5;      // 16 warps
    __shared__ float4 S4[NPTS];                   // 16KB, role-shared
    __shared__ float wred[16];

    const int bx = blockIdx.x;
    if (bx < 128) {
        // ---------------- adjacency ----------------
        const int b = bx >> 2, grp = bx & 3;
        for (int i = tid; i < NPTS; i += 512) {
            const float* xp = x + (size_t)(b*NPTS + i)*FDIM;
            const float p0 = xp[1], p1 = xp[2];
            S4[i] = make_float4(p0, p1, fmaf(p0, p0, p1*p1), 0.f);
        }
        __syncthreads();

        const int jb = grp*8 + (w & 7);
        const int j  = jb*32 + lane;
        const float4 pj = S4[j];
        const float m2p0 = -2.0f*pj.x, m2p1 = -2.0f*pj.y;
        const float cj = C - pj.z;
        float emax = -1e30f;

        const int kq = (w >> 3) * 512;
        unsigned* __restrict__ outp = &g_adjw[((size_t)b*32 + jb)*NPTS];

        for (int kb = 0; kb < 16; kb++) {
            const float4* Pk = &S4[kq + kb*32];
            unsigned myw = 0;
            #pragma unroll 4
            for (int t = 0; t < 32; t++) {
                const float4 pk = Pk[t];                       // broadcast LDS.128
                const float e = fmaf(m2p0, pk.x, fmaf(m2p1, pk.y, pk.z));
                emax = fmaxf(emax, e);
                const unsigned bal = __ballot_sync(0xffffffffu, e < cj);
                if (lane == t) myw = bal;
            }
            outp[kq + kb*32 + lane] = myw;
        }

        float dmax = emax + pj.z;
        #pragma unroll
        for (int s = 16; s > 0; s >>= 1)
            dmax = fmaxf(dmax, __shfl_xor_sync(0xffffffffu, dmax, s));
        if (lane == 0) wred[w] = dmax;
        __syncthreads();
        if (tid == 0) {
            float mx = wred[0];
            #pragma unroll
            for (int i = 1; i < 16; i++) mx = fmaxf(mx, wred[i]);
            g_maxpart[b*4 + grp] = mx;
        }
    } else if (bx < 184) {
        // ---------------- mlp1 partials ----------------
        const int mi = bx - 128;
        const int sl = mi % 7, b0 = (mi / 7)*4;
        float4 (*sx)[256] = reinterpret_cast<float4(*)[256]>(S4);
        for (int q = tid; q < 1024; q += 512) {
            const int bb = q >> 8, e = q & 255;
            sx[bb][e] = ((const float4*)(x + (size_t)(b0 + bb)*(NPTS*FDIM) + sl*1024))[e];
        }
        __syncthreads();

        const int h0 = w*4;
        float acc[4][4];
        #pragma unroll
        for (int r = 0; r < 4; r++)
            #pragma unroll
            for (int bb = 0; bb < 4; bb++) acc[r][bb] = 0.f;

        #pragma unroll
        for (int it = 0; it < 8; it++) {
            const int e = it*32 + lane;
            const float4 x0 = sx[0][e], x1 = sx[1][e], x2 = sx[2][e], x3 = sx[3][e];
            #pragma unroll
            for (int r = 0; r < 4; r++) {
                const float4 wv = ((const float4*)(Wm0 + (size_t)(h0 + r)*(NPTS*FDIM) + sl*1024))[e];
                acc[r][0] = fmaf(wv.x, x0.x, acc[r][0]); acc[r][0] = fmaf(wv.y, x0.y, acc[r][0]);
                acc[r][0] = fmaf(wv.z, x0.z, acc[r][0]); acc[r][0] = fmaf(wv.w, x0.w, acc[r][0]);
                acc[r][1] = fmaf(wv.x, x1.x, acc[r][1]); acc[r][1] = fmaf(wv.y, x1.y, acc[r][1]);
                acc[r][1] = fmaf(wv.z, x1.z, acc[r][1]); acc[r][1] = fmaf(wv.w, x1.w, acc[r][1]);
                acc[r][2] = fmaf(wv.x, x2.x, acc[r][2]); acc[r][2] = fmaf(wv.y, x2.y, acc[r][2]);
                acc[r][2] = fmaf(wv.z, x2.z, acc[r][2]); acc[r][2] = fmaf(wv.w, x2.w, acc[r][2]);
                acc[r][3] = fmaf(wv.x, x3.x, acc[r][3]); acc[r][3] = fmaf(wv.y, x3.y, acc[r][3]);
                acc[r][3] = fmaf(wv.z, x3.z, acc[r][3]); acc[r][3] = fmaf(wv.w, x3.w, acc[r][3]);
            }
        }
        #pragma unroll
        for (int r = 0; r < 4; r++)
            #pragma unroll
            for (int bb = 0; bb < 4; bb++) {
                float v = acc[r][bb];
                #pragma unroll
                for (int s = 16; s > 0; s >>= 1) v += __shfl_xor_sync(0xffffffffu, v, s);
                if (lane == 0) g_mlpPart[((b0 + bb)*7 + sl)*MLP_H + h0 + r] = v;
            }
    } else {
        // ---------------- GCN-head fold: E[o,:] = (Wp_gcn[o,:]@Wfc)@W2 ----------------
        const int o = bx - 184;
        const float* wp = Wp + (size_t)o*(MLP_H + HID + OUTD) + MLP_H;   // Wp_gcn row o
        float* sA = (float*)S4;

        if (tid < HID) {
            float a = 0.f;
            #pragma unroll 8
            for (int k = 0; k < HID; k++)
                a = fmaf(wp[k], Wfc[(size_t)k*HID + tid], a);
            sA[tid] = a;
        }
        __syncthreads();

        float v = (tid < HID) ? fmaf(sA[tid], b2[tid], wp[tid]*bfc[tid]) : 0.f;
        #pragma unroll
        for (int s = 16; s > 0; s >>= 1) v += __shfl_xor_sync(0xffffffffu, v, s);
        if (lane == 0) wred[w] = v;
        __syncthreads();
        if (tid == 0) {
            float c = 0.f;
            #pragma unroll
            for (int i = 0; i < 8; i++) c += wred[i];
            g_c0[o] = c;
        }

        if (tid < HID) {
            float e = 0.f;
            #pragma unroll 8
            for (int k = 0; k < HID; k++)
                e = fmaf(sA[k], W2[(size_t)k*HID + tid], e);
            g_E[o*HID + tid] = e;
        }
    }
}

// ---------------- K2: per-batch megakernel — gather, upart, m, head, output ----------------
__global__ void __launch_bounds__(1024)
k2(const float* __restrict__ x,
   const float* __restrict__ W1, const float* __restrict__ b1,
   const float* __restrict__ Wg, const float* __restrict__ bgv,
   const float* __restrict__ Wm1, const float* __restrict__ bm1,
   const float* __restrict__ bm0,
   const float* __restrict__ Wp, const float* __restrict__ bp,
   float* __restrict__ out) {
    const int b = blockIdx.x;
    const int j = threadIdx.x;
    const int lane = j & 31, wid = j >> 5;

    __shared__ float sp0[NPTS], sp1[NPTS], sdv[NPTS];   // later reused as pp0/pp1/cc
    __shared__ float red[32];
    __shared__ float part[4][HID];
    __shared__ float sm[HID];
    __shared__ float m0[MLP_H], m1[MLP_H], glo8[OUTD];
    __shared__ float sgl[2];

    // ---- phase 1: per-row degree + sparse gather (gup) ----
    const float* xp = x + (size_t)(b*NPTS + j)*FDIM;
    const float p0 = xp[1], p1 = xp[2];
    const float x3 = xp[3], x4 = xp[4];
    sp0[j] = p0; sp1[j] = p1;
    float sp = sqrtf(fmaf(x3, x3, x4*x4));

    unsigned wr[32]; int cnt = 0;
    #pragma unroll
    for (int cb = 0; cb < 32; cb++) {
        wr[cb] = g_adjw[((size_t)b*32 + cb)*NPTS + j];
        cnt += __popc(wr[cb]);
    }
    const float dinv = 1.0f / sqrtf((float)cnt);
    sdv[j] = dinv;

    #pragma unroll
    for (int s = 16; s > 0; s >>= 1) sp += __shfl_xor_sync(0xffffffffu, sp, s);
    if (lane == 0) red[wid] = sp;
    __syncthreads();

    float s0 = 0.f, s1 = 0.f, t = 0.f;
    for (int cb = 0; cb < 32; cb++) {
        unsigned m = wr[cb];
        const int base = cb*32;
        while (m) {
            const int i = __ffs(m) - 1;
            m &= m - 1;
            const int k = base + i;
            const float d = sdv[k];
            s0 = fmaf(d, sp0[k], s0);
            s1 = fmaf(d, sp1[k], s1);
            t += d;
        }
    }
    const float r0 = dinv*s0, r1 = dinv*s1, r2 = dinv*t;

    if (wid == 0) {
        float v = red[lane];
        #pragma unroll
        for (int s = 16; s > 0; s >>= 1) v += __shfl_xor_sync(0xffffffffu, v, s);
        if (lane == 0) {
            float mx = fmaxf(fmaxf(g_maxpart[b*4+0], g_maxpart[b*4+1]),
                             fmaxf(g_maxpart[b*4+2], g_maxpart[b*4+3]));
            sgl[0] = v * (1.0f/1024.0f);
            sgl[1] = 1.0f / sqrtf(mx);
        }
    }
    __syncthreads();                 // all gather reads done
    sp0[j] = r0; sp1[j] = r1; sdv[j] = r2;   // reuse as pp0/pp1/cc
    __syncthreads();

    // ---- phase 2: u partials (upart) — dim d, quarter q ----
    {
        const int d = j & 255, q = j >> 8;
        const float w0 = W1[2*d], w1 = W1[2*d + 1], bd = b1[d];
        const int nb = q*256;
        float a0 = 0.f, a1 = 0.f, a2 = 0.f, a3 = 0.f;
        #pragma unroll 4
        for (int i = 0; i < 64; i++) {
            const int n0 = nb + i, n1 = nb + 64 + i, n2 = nb + 128 + i, n3 = nb + 192 + i;
            float t0 = fmaf(w1, sp1[n0], fmaf(w0, sp0[n0], bd)); t0 = fmaxf(t0, 0.f);
            float t1 = fmaf(w1, sp1[n1], fmaf(w0, sp0[n1], bd)); t1 = fmaxf(t1, 0.f);
            float t2 = fmaf(w1, sp1[n2], fmaf(w0, sp0[n2], bd)); t2 = fmaxf(t2, 0.f);
            float t3 = fmaf(w1, sp1[n3], fmaf(w0, sp0[n3], bd)); t3 = fmaxf(t3, 0.f);
            a0 = fmaf(sdv[n0], t0, a0);
            a1 = fmaf(sdv[n1], t1, a1);
            a2 = fmaf(sdv[n2], t2, a2);
            a3 = fmaf(sdv[n3], t3, a3);
        }
        part[q][d] = (a0 + a1) + (a2 + a3);
    }
    __syncthreads();

    // ---- phase 3: m, m0, glo ----
    if (j < HID)
        sm[j] = (part[0][j] + part[1][j] + part[2][j] + part[3][j]) * (1.0f/1024.0f);
    else if (j >= 512 && j < 512 + MLP_H) {
        const int h = j - 512;
        float a = bm0[h];
        #pragma unroll
        for (int s = 0; s < 7; s++) a += g_mlpPart[(b*7 + s)*MLP_H + h];
        m0[h] = fmaxf(a, 0.f);
    } else if (j >= 768 && j < 768 + OUTD) {
        const int o = j - 768;
        const float ge = fmaf(Wg[2*o], sgl[0], fmaf(Wg[2*o + 1], sgl[1], bgv[o]));
        glo8[o] = fmaxf(ge, 0.f);
    }
    __syncthreads();

    // ---- phase 4: mlp layer 2 (64 outputs x 4 threads) ----
    if (j < 256) {
        const int od = j >> 2, q = j & 3;
        const float4* wr4 = (const float4*)(Wm1 + (size_t)od*MLP_H + q*16);
        const float4* mm4 = (const float4*)(m0 + q*16);
        float p = 0.f;
        #pragma unroll
        for (int e = 0; e < 4; e++) {
            const float4 wv = wr4[e], mv = mm4[e];
            p = fmaf(wv.x, mv.x, p); p = fmaf(wv.y, mv.y, p);
            p = fmaf(wv.z, mv.z, p); p = fmaf(wv.w, mv.w, p);
        }
        p += __shfl_xor_sync(0xffffffffu, p, 1);
        p += __shfl_xor_sync(0xffffffffu, p, 2);
        if (q == 0) m1[od] = fmaxf(p + bm1[od], 0.f);
    }
    __syncthreads();

    // ---- phase 5: output — warp o in [0,8) ----
    if (wid < OUTD) {
        const int o = wid;
        const float* Eo = g_E + o*HID;
        const float* wp = Wp + (size_t)o*(MLP_H + HID + OUTD);
        float p = 0.f;
        #pragma unroll
        for (int c = 0; c < 8; c++)
            p = fmaf(Eo[c*32 + lane], sm[c*32 + lane], p);
        p = fmaf(wp[lane],      m1[lane],      p);
        p = fmaf(wp[32 + lane], m1[32 + lane], p);
        if (lane < OUTD) p = fmaf(wp[320 + lane], glo8[lane], p);
        #pragma unroll
        for (int s = 16; s > 0; s >>= 1) p += __shfl_xor_sync(0xffffffffu, p, s);
        if (lane == 0) out[b*OUTD + o] = p + bp[o] + g_c0[o];
    }
}

// ---------------- launch ----------------
extern "C" void kernel_launch(void* const* d_in, const int* in_sizes, int n_in,
                              void* d_out, int out_size) {
    (void)in_sizes; (void)n_in; (void)out_size;
    const float* x   = (const float*)d_in[0];
    const float* W1  = (const float*)d_in[1];
    const float* b1  = (const float*)d_in[2];
    const float* W2  = (const float*)d_in[3];
    const float* b2  = (const float*)d_in[4];
    const float* Wfc = (const float*)d_in[5];
    const float* bfc = (const float*)d_in[6];
    const float* Wg  = (const float*)d_in[7];
    const float* bg  = (const float*)d_in[8];
    const float* Wm0 = (const float*)d_in[9];
    const float* bm0 = (const float*)d_in[10];
    const float* Wm1 = (const float*)d_in[11];
    const float* bm1 = (const float*)d_in[12];
    const float* Wp  = (const float*)d_in[13];
    const float* bp  = (const float*)d_in[14];
    float* out = (float*)d_out;

    // smallest C with sqrtf(C) >= 0.3f  =>  (d2 < C) <=> (sqrtf(d2) < 0.3f)
    float C = 0.09f;
    while (sqrtf(C) >= 0.3f) C = nextafterf(C, 0.0f);
    while (sqrtf(C) <  0.3f) C = nextafterf(C, 1.0f);

    kA<<<192, 512>>>(x, Wm0, Wfc, W2, b2, bfc, Wp, C);
    k2<<<BATCH, 1024>>>(x, W1, b1, Wg, bg, Wm1, bm1, bm0, Wp, bp, out);
}

// round 7
// speedup vs baseline: 1.1896x; 1.0745x over previous
#include <cuda_runtime.h>
#include <cuda_bf16.h>
#include <cmath>

#define BATCH 32
#define NPTS  1024
#define FDIM  7
#define HID   256
#define MLP_H 64
#define OUTD  8

// ---------------- scratch (device globals) ----------------
__device__ unsigned g_adjw[BATCH*32*NPTS];        // adjacency bitmask, 4 MB
__device__ float    g_maxpart[BATCH*4];
__device__ float    g_mlpPart[BATCH*7*MLP_H];
__device__ float    g_upart[BATCH*8*HID];
__device__ float    g_E[OUTD*HID];                // folded GCN head: Wp_gcn@Wfc@W2
__device__ float    g_c0[OUTD];                   // folded GCN bias contribution

// ---------------- KA: fused adjacency + MLP layer-1 + GCN-head fold ----------------
// blocks [0,128): adjacency (b = bx>>2, j-group = bx&3)
// blocks [128,184): mlp1 partials (7 slices x 8 batch-groups)
// blocks [184,192): GCN-head fold, one block per output row o
__global__ void __launch_bounds__(512)
kA(const float* __restrict__ x, const float* __restrict__ Wm0,
   const float* __restrict__ Wfc, const float* __restrict__ W2,
   const float* __restrict__ b2, const float* __restrict__ bfc,
   const float* __restrict__ Wp, float C) {
    const int tid = threadIdx.x;
    const int lane = tid & 31, w = tid >> 5;      // 16 warps
    __shared__ float4 S4[NPTS];                   // 16KB, role-shared
    __shared__ float wred[16];

    const int bx = blockIdx.x;
    if (bx < 128) {
        // ---------------- adjacency ----------------
        const int b = bx >> 2, grp = bx & 3;
        for (int i = tid; i < NPTS; i += 512) {
            const float* xp = x + (size_t)(b*NPTS + i)*FDIM;
            const float p0 = xp[1], p1 = xp[2];
            S4[i] = make_float4(p0, p1, fmaf(p0, p0, p1*p1), 0.f);
        }
        __syncthreads();

        const int jb = grp*8 + (w & 7);
        const int j  = jb*32 + lane;
        const float4 pj = S4[j];
        const float m2p0 = -2.0f*pj.x, m2p1 = -2.0f*pj.y;
        const float cj = C - pj.z;
        float emax = -1e30f;

        const int kq = (w >> 3) * 512;
        unsigned* __restrict__ outp = &g_adjw[((size_t)b*32 + jb)*NPTS];

        for (int kb = 0; kb < 16; kb++) {
            const float4* Pk = &S4[kq + kb*32];
            unsigned myw = 0;
            #pragma unroll 4
            for (int t = 0; t < 32; t++) {
                const float4 pk = Pk[t];                       // broadcast LDS.128
                const float e = fmaf(m2p0, pk.x, fmaf(m2p1, pk.y, pk.z));
                emax = fmaxf(emax, e);
                const unsigned bal = __ballot_sync(0xffffffffu, e < cj);
                if (lane == t) myw = bal;
            }
            outp[kq + kb*32 + lane] = myw;
        }

        float dmax = emax + pj.z;
        #pragma unroll
        for (int s = 16; s > 0; s >>= 1)
            dmax = fmaxf(dmax, __shfl_xor_sync(0xffffffffu, dmax, s));
        if (lane == 0) wred[w] = dmax;
        __syncthreads();
        if (tid == 0) {
            float mx = wred[0];
            #pragma unroll
            for (int i = 1; i < 16; i++) mx = fmaxf(mx, wred[i]);
            g_maxpart[b*4 + grp] = mx;
        }
    } else if (bx < 184) {
        // ---------------- mlp1 partials ----------------
        const int mi = bx - 128;
        const int sl = mi % 7, b0 = (mi / 7)*4;
        float4 (*sx)[256] = reinterpret_cast<float4(*)[256]>(S4);
        for (int q = tid; q < 1024; q += 512) {
            const int bb = q >> 8, e = q & 255;
            sx[bb][e] = ((const float4*)(x + (size_t)(b0 + bb)*(NPTS*FDIM) + sl*1024))[e];
        }
        __syncthreads();

        const int h0 = w*4;
        float acc[4][4];
        #pragma unroll
        for (int r = 0; r < 4; r++)
            #pragma unroll
            for (int bb = 0; bb < 4; bb++) acc[r][bb] = 0.f;

        #pragma unroll
        for (int it = 0; it < 8; it++) {
            const int e = it*32 + lane;
            const float4 x0 = sx[0][e], x1 = sx[1][e], x2 = sx[2][e], x3 = sx[3][e];
            #pragma unroll
            for (int r = 0; r < 4; r++) {
                const float4 wv = ((const float4*)(Wm0 + (size_t)(h0 + r)*(NPTS*FDIM) + sl*1024))[e];
                acc[r][0] = fmaf(wv.x, x0.x, acc[r][0]); acc[r][0] = fmaf(wv.y, x0.y, acc[r][0]);
                acc[r][0] = fmaf(wv.z, x0.z, acc[r][0]); acc[r][0] = fmaf(wv.w, x0.w, acc[r][0]);
                acc[r][1] = fmaf(wv.x, x1.x, acc[r][1]); acc[r][1] = fmaf(wv.y, x1.y, acc[r][1]);
                acc[r][1] = fmaf(wv.z, x1.z, acc[r][1]); acc[r][1] = fmaf(wv.w, x1.w, acc[r][1]);
                acc[r][2] = fmaf(wv.x, x2.x, acc[r][2]); acc[r][2] = fmaf(wv.y, x2.y, acc[r][2]);
                acc[r][2] = fmaf(wv.z, x2.z, acc[r][2]); acc[r][2] = fmaf(wv.w, x2.w, acc[r][2]);
                acc[r][3] = fmaf(wv.x, x3.x, acc[r][3]); acc[r][3] = fmaf(wv.y, x3.y, acc[r][3]);
                acc[r][3] = fmaf(wv.z, x3.z, acc[r][3]); acc[r][3] = fmaf(wv.w, x3.w, acc[r][3]);
            }
        }
        #pragma unroll
        for (int r = 0; r < 4; r++)
            #pragma unroll
            for (int bb = 0; bb < 4; bb++) {
                float v = acc[r][bb];
                #pragma unroll
                for (int s = 16; s > 0; s >>= 1) v += __shfl_xor_sync(0xffffffffu, v, s);
                if (lane == 0) g_mlpPart[((b0 + bb)*7 + sl)*MLP_H + h0 + r] = v;
            }
    } else {
        // ---------------- GCN-head fold: E[o,:] = (Wp_gcn[o,:]@Wfc)@W2 ----------------
        const int o = bx - 184;
        const float* wp = Wp + (size_t)o*(MLP_H + HID + OUTD) + MLP_H;   // Wp_gcn row o
        float* sA = (float*)S4;

        if (tid < HID) {
            float a = 0.f;
            #pragma unroll 8
            for (int k = 0; k < HID; k++)
                a = fmaf(wp[k], Wfc[(size_t)k*HID + tid], a);
            sA[tid] = a;
        }
        __syncthreads();

        float v = (tid < HID) ? fmaf(sA[tid], b2[tid], wp[tid]*bfc[tid]) : 0.f;
        #pragma unroll
        for (int s = 16; s > 0; s >>= 1) v += __shfl_xor_sync(0xffffffffu, v, s);
        if (lane == 0) wred[w] = v;
        __syncthreads();
        if (tid == 0) {
            float c = 0.f;
            #pragma unroll
            for (int i = 0; i < 8; i++) c += wred[i];
            g_c0[o] = c;
        }

        if (tid < HID) {
            float e = 0.f;
            #pragma unroll 8
            for (int k = 0; k < HID; k++)
                e = fmaf(sA[k], W2[(size_t)k*HID + tid], e);
            g_E[o*HID + tid] = e;
        }
    }
}

// ---------------- K2a: degrees + gather (2 thr/row) + u-partials, quarter-batch blocks ----------------
__global__ void __launch_bounds__(512)
k2a(const float* __restrict__ x,
    const float* __restrict__ W1, const float* __restrict__ b1) {
    const int q = blockIdx.x, b = blockIdx.y;     // quarter q of batch b
    const int t = threadIdx.x;

    __shared__ float sp0[NPTS], sp1[NPTS], sdv[NPTS];
    __shared__ float4 P4[256];                    // (pp0, pp1, cc, 0) for own rows
    __shared__ float g0[256], g1[256], g2[256];   // half-1 gather partials

    // points
    for (int i = t; i < NPTS; i += 512) {
        const float* xp = x + (size_t)(b*NPTS + i)*FDIM;
        sp0[i] = xp[1];
        sp1[i] = xp[2];
    }
    // degrees for ALL rows (2 rows/thread)
    for (int r = t; r < NPTS; r += 512) {
        int cnt = 0;
        #pragma unroll
        for (int cb = 0; cb < 32; cb++)
            cnt += __popc(g_adjw[((size_t)b*32 + cb)*NPTS + r]);
        sdv[r] = 1.0f / sqrtf((float)cnt);
    }
    __syncthreads();

    // gather for own 256 rows, 2 threads per row (16 words each)
    const int rloc = t & 255;
    const int rr   = q*256 + rloc;
    const int half = t >> 8;
    float s0 = 0.f, s1 = 0.f, ss = 0.f;
    for (int cb = half*16; cb < half*16 + 16; cb++) {
        unsigned m = g_adjw[((size_t)b*32 + cb)*NPTS + rr];
        const int base = cb*32;
        while (m) {
            const int i = __ffs(m) - 1;
            m &= m - 1;
            const int k = base + i;
            const float d = sdv[k];
            s0 = fmaf(d, sp0[k], s0);
            s1 = fmaf(d, sp1[k], s1);
            ss += d;
        }
    }
    if (half == 1) { g0[rloc] = s0; g1[rloc] = s1; g2[rloc] = ss; }
    __syncthreads();
    if (half == 0) {
        const float dj = sdv[rr];
        P4[rloc] = make_float4(dj*(s0 + g0[rloc]), dj*(s1 + g1[rloc]),
                               dj*(ss + g2[rloc]), 0.f);
    }
    __syncthreads();

    // u partial: dim d over this block's 256 points, split in 2 halves
    {
        const int d = t & 255;
        const float w0 = W1[2*d], w1 = W1[2*d + 1], bd = b1[d];
        const int pb = half*128;
        float a0 = 0.f, a1 = 0.f;
        #pragma unroll 4
        for (int i = 0; i < 64; i++) {
            const float4 v0 = P4[pb + i];
            const float4 v1 = P4[pb + 64 + i];
            float t0 = fmaf(w1, v0.y, fmaf(w0, v0.x, bd)); t0 = fmaxf(t0, 0.f);
            float t1 = fmaf(w1, v1.y, fmaf(w0, v1.x, bd)); t1 = fmaxf(t1, 0.f);
            a0 = fmaf(v0.z, t0, a0);
            a1 = fmaf(v1.z, t1, a1);
        }
        g_upart[((size_t)b*8 + q*2 + half)*HID + d] = a0 + a1;
    }
}

// ---------------- K2b: speed, m, glo, mlp finish, folded-head output ----------------
__global__ void __launch_bounds__(1024)
k2b(const float* __restrict__ x,
    const float* __restrict__ Wg, const float* __restrict__ bgv,
    const float* __restrict__ Wm1, const float* __restrict__ bm1,
    const float* __restrict__ bm0,
    const float* __restrict__ Wp, const float* __restrict__ bp,
    float* __restrict__ out) {
    const int b = blockIdx.x;
    const int t = threadIdx.x;
    const int lane = t & 31, wid = t >> 5;

    __shared__ float red[32];
    __shared__ float sm[HID];
    __shared__ float m0[MLP_H], m1[MLP_H], glo8[OUTD];
    __shared__ float sgl[2];

    // speed sum over 1024 points
    {
        const float* xp = x + (size_t)(b*NPTS + t)*FDIM;
        const float x3 = xp[3], x4 = xp[4];
        float sp = sqrtf(fmaf(x3, x3, x4*x4));
        #pragma unroll
        for (int s = 16; s > 0; s >>= 1) sp += __shfl_xor_sync(0xffffffffu, sp, s);
        if (lane == 0) red[wid] = sp;
    }
    if (t < HID) {
        float u = 0.f;
        #pragma unroll
        for (int c = 0; c < 8; c++) u += g_upart[((size_t)b*8 + c)*HID + t];
        sm[t] = u * (1.0f/1024.0f);
    } else if (t >= 512 && t < 512 + MLP_H) {
        const int h = t - 512;
        float a = bm0[h];
        #pragma unroll
        for (int s = 0; s < 7; s++) a += g_mlpPart[(b*7 + s)*MLP_H + h];
        m0[h] = fmaxf(a, 0.f);
    }
    __syncthreads();

    if (wid == 0) {
        float v = red[lane];
        #pragma unroll
        for (int s = 16; s > 0; s >>= 1) v += __shfl_xor_sync(0xffffffffu, v, s);
        if (lane == 0) {
            float mx = fmaxf(fmaxf(g_maxpart[b*4+0], g_maxpart[b*4+1]),
                             fmaxf(g_maxpart[b*4+2], g_maxpart[b*4+3]));
            sgl[0] = v * (1.0f/1024.0f);
            sgl[1] = 1.0f / sqrtf(mx);
        }
    }
    __syncthreads();

    if (t >= 768 && t < 768 + OUTD) {
        const int o = t - 768;
        const float ge = fmaf(Wg[2*o], sgl[0], fmaf(Wg[2*o + 1], sgl[1], bgv[o]));
        glo8[o] = fmaxf(ge, 0.f);
    }
    // mlp layer 2: 64 outputs x 4 threads
    if (t < 256) {
        const int od = t >> 2, qq = t & 3;
        const float4* wr4 = (const float4*)(Wm1 + (size_t)od*MLP_H + qq*16);
        const float4* mm4 = (const float4*)(m0 + qq*16);
        float p = 0.f;
        #pragma unroll
        for (int e = 0; e < 4; e++) {
            const float4 wv = wr4[e], mv = mm4[e];
            p = fmaf(wv.x, mv.x, p); p = fmaf(wv.y, mv.y, p);
            p = fmaf(wv.z, mv.z, p); p = fmaf(wv.w, mv.w, p);
        }
        p += __shfl_xor_sync(0xffffffffu, p, 1);
        p += __shfl_xor_sync(0xffffffffu, p, 2);
        if (qq == 0) m1[od] = fmaxf(p + bm1[od], 0.f);
    }
    __syncthreads();

    // output: warp o in [0,8)
    if (wid < OUTD) {
        const int o = wid;
        const float* Eo = g_E + o*HID;
        const float* wp = Wp + (size_t)o*(MLP_H + HID + OUTD);
        float p = 0.f;
        #pragma unroll
        for (int c = 0; c < 8; c++)
            p = fmaf(Eo[c*32 + lane], sm[c*32 + lane], p);
        p = fmaf(wp[lane],      m1[lane],      p);
        p = fmaf(wp[32 + lane], m1[32 + lane], p);
        if (lane < OUTD) p = fmaf(wp[320 + lane], glo8[lane], p);
        #pragma unroll
        for (int s = 16; s > 0; s >>= 1) p += __shfl_xor_sync(0xffffffffu, p, s);
        if (lane == 0) out[b*OUTD + o] = p + bp[o] + g_c0[o];
    }
}

// ---------------- launch ----------------
extern "C" void kernel_launch(void* const* d_in, const int* in_sizes, int n_in,
                              void* d_out, int out_size) {
    (void)in_sizes; (void)n_in; (void)out_size;
    const float* x   = (const float*)d_in[0];
    const float* W1  = (const float*)d_in[1];
    const float* b1  = (const float*)d_in[2];
    const float* W2  = (const float*)d_in[3];
    const float* b2  = (const float*)d_in[4];
    const float* Wfc = (const float*)d_in[5];
    const float* bfc = (const float*)d_in[6];
    const float* Wg  = (const float*)d_in[7];
    const float* bg  = (const float*)d_in[8];
    const float* Wm0 = (const float*)d_in[9];
    const float* bm0 = (const float*)d_in[10];
    const float* Wm1 = (const float*)d_in[11];
    const float* bm1 = (const float*)d_in[12];
    const float* Wp  = (const float*)d_in[13];
    const float* bp  = (const float*)d_in[14];
    float* out = (float*)d_out;

    // smallest C with sqrtf(C) >= 0.3f  =>  (d2 < C) <=> (sqrtf(d2) < 0.3f)
    float C = 0.09f;
    while (sqrtf(C) >= 0.3f) C = nextafterf(C, 0.0f);
    while (sqrtf(C) <  0.3f) C = nextafterf(C, 1.0f);

    kA <<<192, 512>>>(x, Wm0, Wfc, W2, b2, bfc, Wp, C);
    k2a<<<dim3(4, BATCH), 512>>>(x, W1, b1);
    k2b<<<BATCH, 1024>>>(x, Wg, bg, Wm1, bm1, bm0, Wp, bp, out);
}

// round 9
// speedup vs baseline: 1.5481x; 1.3013x over previous
#include <cuda_runtime.h>
#include <cuda_bf16.h>
#include <cmath>

#define BATCH 32
#define NPTS  1024
#define FDIM  7
#define HID   256
#define MLP_H 64
#define OUTD  8

// ---------------- scratch (device globals) ----------------
__device__ unsigned g_adjw[BATCH*32*NPTS];        // adjacency bitmask, 4 MB
__device__ float    g_maxpart[BATCH*4];
__device__ float    g_mlpPart[BATCH*7*MLP_H];
__device__ float    g_upart[BATCH*8*HID];
__device__ float    g_E[OUTD*HID];                // folded GCN head: Wp_gcn@Wfc@W2
__device__ float    g_c0[OUTD];                   // folded GCN bias contribution

// ---------------- KA: fused adjacency(sym bit-build) + MLP layer-1 + GCN-head fold ----------------
// blocks [0,128): adjacency (b = bx>>2, warp-quarter group = bx&3)
// blocks [128,184): mlp1 partials (7 slices x 8 batch-groups)
// blocks [184,192): GCN-head fold, one block per output row o
__global__ void __launch_bounds__(512)
kA(const float* __restrict__ x, const float* __restrict__ Wm0,
   const float* __restrict__ Wfc, const float* __restrict__ W2,
   const float* __restrict__ b2, const float* __restrict__ bfc,
   const float* __restrict__ Wp, float C) {
    const int tid = threadIdx.x;
    const int lane = tid & 31, w = tid >> 5;      // 16 warps
    __shared__ float4 S4[NPTS];                   // 16KB, role-shared
    __shared__ float wred[16];

    const int bx = blockIdx.x;
    if (bx < 128) {
        // ---------------- adjacency: upper-tri tiles, per-lane bit-build, mirror by transpose ----------------
        const int b = bx >> 2;
        for (int i = tid; i < NPTS; i += 512) {
            const float* xp = x + (size_t)(b*NPTS + i)*FDIM;
            const float p0 = xp[1], p1 = xp[2];
            const float n = fmaf(p0, p0, p1*p1);
            S4[i] = make_float4(p0, p1, n, C - n);
        }
        __syncthreads();

        const int ww = (bx & 3)*16 + w;           // warp id within batch, 0..63
        const int p  = ww >> 2;                   // balanced pair 0..15 (rows p and 31-p)
        const int qh = ww & 3;                    // quarter of the 33 tiles
        const int i0 = (33*qh) >> 2, i1 = (33*(qh + 1)) >> 2;

        unsigned* __restrict__ aw = &g_adjw[(size_t)b*32*NPTS];
        float mx0 = -1e30f, mx1 = -1e30f;

        for (int idx = i0; idx < i1; idx++) {
            int jb, kb;
            if (idx < 32 - p) { jb = p;      kb = p + idx; }
            else              { jb = 31 - p; kb = idx - 1; }

            const float4 pk = S4[kb*32 + lane];
            const float a0 = -2.0f*pk.x, a1 = -2.0f*pk.y, nk = pk.z;
            const float4* Pj = &S4[jb*32];

            unsigned w0 = 0, w1 = 0;
            #pragma unroll
            for (int t = 0; t < 32; t++) {
                const float4 pj = Pj[t];                      // broadcast LDS.128
                float u = fmaf(a0, pj.x, nk);
                u = fmaf(a1, pj.y, u);                        // u = nk - 2 pj.pk
                if (t & 1) { if (u < pj.w) w1 |= (1u << t); mx1 = fmaxf(mx1, u + pj.z); }
                else       { if (u < pj.w) w0 |= (1u << t); mx0 = fmaxf(mx0, u + pj.z); }
            }
            const unsigned word = w0 | w1;
            aw[(jb << 10) + kb*32 + lane] = word;             // row kb*32+lane, colblock jb

            if (jb != kb) {
                // warp 32x32 bit-matrix transpose (mirror tile)
                unsigned xw = word;
                #pragma unroll
                for (int i2 = 4; i2 >= 0; i2--) {
                    const int s = 1 << i2;
                    const unsigned msk = (i2 == 4) ? 0x0000FFFFu :
                                         (i2 == 3) ? 0x00FF00FFu :
                                         (i2 == 2) ? 0x0F0F0F0Fu :
                                         (i2 == 1) ? 0x33333333u : 0x55555555u;
                    const unsigned y = __shfl_xor_sync(0xffffffffu, xw, s);
                    xw = (lane & s) ? ((xw & ~msk) | ((y >> s) & msk))
                                    : ((xw & msk) | ((y & msk) << s));
                }
                aw[(kb << 10) + jb*32 + lane] = xw;           // row jb*32+lane, colblock kb
            }
        }

        float dmax = fmaxf(mx0, mx1);
        #pragma unroll
        for (int s = 16; s > 0; s >>= 1)
            dmax = fmaxf(dmax, __shfl_xor_sync(0xffffffffu, dmax, s));
        if (lane == 0) wred[w] = dmax;
        __syncthreads();
        if (tid == 0) {
            float mx = wred[0];
            #pragma unroll
            for (int i = 1; i < 16; i++) mx = fmaxf(mx, wred[i]);
            g_maxpart[b*4 + (bx & 3)] = mx;
        }
    } else if (bx < 184) {
        // ---------------- mlp1 partials ----------------
        const int mi = bx - 128;
        const int sl = mi % 7, b0 = (mi / 7)*4;
        float4 (*sx)[256] = reinterpret_cast<float4(*)[256]>(S4);
        for (int q = tid; q < 1024; q += 512) {
            const int bb = q >> 8, e = q & 255;
            sx[bb][e] = ((const float4*)(x + (size_t)(b0 + bb)*(NPTS*FDIM) + sl*1024))[e];
        }
        __syncthreads();

        const int h0 = w*4;
        float acc[4][4];
        #pragma unroll
        for (int r = 0; r < 4; r++)
            #pragma unroll
            for (int bb = 0; bb < 4; bb++) acc[r][bb] = 0.f;

        #pragma unroll
        for (int it = 0; it < 8; it++) {
            const int e = it*32 + lane;
            const float4 x0 = sx[0][e], x1 = sx[1][e], x2 = sx[2][e], x3 = sx[3][e];
            #pragma unroll
            for (int r = 0; r < 4; r++) {
                const float4 wv = ((const float4*)(Wm0 + (size_t)(h0 + r)*(NPTS*FDIM) + sl*1024))[e];
                acc[r][0] = fmaf(wv.x, x0.x, acc[r][0]); acc[r][0] = fmaf(wv.y, x0.y, acc[r][0]);
                acc[r][0] = fmaf(wv.z, x0.z, acc[r][0]); acc[r][0] = fmaf(wv.w, x0.w, acc[r][0]);
                acc[r][1] = fmaf(wv.x, x1.x, acc[r][1]); acc[r][1] = fmaf(wv.y, x1.y, acc[r][1]);
                acc[r][1] = fmaf(wv.z, x1.z, acc[r][1]); acc[r][1] = fmaf(wv.w, x1.w, acc[r][1]);
                acc[r][2] = fmaf(wv.x, x2.x, acc[r][2]); acc[r][2] = fmaf(wv.y, x2.y, acc[r][2]);
                acc[r][2] = fmaf(wv.z, x2.z, acc[r][2]); acc[r][2] = fmaf(wv.w, x2.w, acc[r][2]);
                acc[r][3] = fmaf(wv.x, x3.x, acc[r][3]); acc[r][3] = fmaf(wv.y, x3.y, acc[r][3]);
                acc[r][3] = fmaf(wv.z, x3.z, acc[r][3]); acc[r][3] = fmaf(wv.w, x3.w, acc[r][3]);
            }
        }
        #pragma unroll
        for (int r = 0; r < 4; r++)
            #pragma unroll
            for (int bb = 0; bb < 4; bb++) {
                float v = acc[r][bb];
                #pragma unroll
                for (int s = 16; s > 0; s >>= 1) v += __shfl_xor_sync(0xffffffffu, v, s);
                if (lane == 0) g_mlpPart[((b0 + bb)*7 + sl)*MLP_H + h0 + r] = v;
            }
    } else {
        // ---------------- GCN-head fold: E[o,:] = (Wp_gcn[o,:]@Wfc)@W2 ----------------
        const int o = bx - 184;
        const float* wp = Wp + (size_t)o*(MLP_H + HID + OUTD) + MLP_H;   // Wp_gcn row o
        float* sA = (float*)S4;

        if (tid < HID) {
            float a = 0.f;
            #pragma unroll 8
            for (int k = 0; k < HID; k++)
                a = fmaf(wp[k], Wfc[(size_t)k*HID + tid], a);
            sA[tid] = a;
        }
        __syncthreads();

        float v = (tid < HID) ? fmaf(sA[tid], b2[tid], wp[tid]*bfc[tid]) : 0.f;
        #pragma unroll
        for (int s = 16; s > 0; s >>= 1) v += __shfl_xor_sync(0xffffffffu, v, s);
        if (lane == 0) wred[w] = v;
        __syncthreads();
        if (tid == 0) {
            float c = 0.f;
            #pragma unroll
            for (int i = 0; i < 8; i++) c += wred[i];
            g_c0[o] = c;
        }

        if (tid < HID) {
            float e = 0.f;
            #pragma unroll 8
            for (int k = 0; k < HID; k++)
                e = fmaf(sA[k], W2[(size_t)k*HID + tid], e);
            g_E[o*HID + tid] = e;
        }
    }
}

// ---------------- K2a: degrees + gather (2 thr/row) + u-partials, quarter-batch blocks ----------------
__global__ void __launch_bounds__(512)
k2a(const float* __restrict__ x,
    const float* __restrict__ W1, const float* __restrict__ b1) {
    const int q = blockIdx.x, b = blockIdx.y;     // quarter q of batch b
    const int t = threadIdx.x;

    __shared__ float sp0[NPTS], sp1[NPTS], sdv[NPTS];
    __shared__ float4 P4[256];                    // (pp0, pp1, cc, 0) for own rows
    __shared__ float g0[256], g1[256], g2[256];   // half-1 gather partials

    for (int i = t; i < NPTS; i += 512) {
        const float* xp = x + (size_t)(b*NPTS + i)*FDIM;
        sp0[i] = xp[1];
        sp1[i] = xp[2];
    }
    for (int r = t; r < NPTS; r += 512) {
        int cnt = 0;
        #pragma unroll
        for (int cb = 0; cb < 32; cb++)
            cnt += __popc(g_adjw[((size_t)b*32 + cb)*NPTS + r]);
        sdv[r] = 1.0f / sqrtf((float)cnt);
    }
    __syncthreads();

    const int rloc = t & 255;
    const int rr   = q*256 + rloc;
    const int half = t >> 8;
    float s0 = 0.f, s1 = 0.f, ss = 0.f;
    for (int cb = half*16; cb < half*16 + 16; cb++) {
        unsigned m = g_adjw[((size_t)b*32 + cb)*NPTS + rr];
        const int base = cb*32;
        while (m) {
            const int i = __ffs(m) - 1;
            m &= m - 1;
            const int k = base + i;
            const float d = sdv[k];
            s0 = fmaf(d, sp0[k], s0);
            s1 = fmaf(d, sp1[k], s1);
            ss += d;
        }
    }
    if (half == 1) { g0[rloc] = s0; g1[rloc] = s1; g2[rloc] = ss; }
    __syncthreads();
    if (half == 0) {
        const float dj = sdv[rr];
        P4[rloc] = make_float4(dj*(s0 + g0[rloc]), dj*(s1 + g1[rloc]),
                               dj*(ss + g2[rloc]), 0.f);
    }
    __syncthreads();

    {
        const int d = t & 255;
        const float w0 = W1[2*d], w1 = W1[2*d + 1], bd = b1[d];
        const int pb = half*128;
        float a0 = 0.f, a1 = 0.f;
        #pragma unroll 4
        for (int i = 0; i < 64; i++) {
            const float4 v0 = P4[pb + i];
            const float4 v1 = P4[pb + 64 + i];
            float t0 = fmaf(w1, v0.y, fmaf(w0, v0.x, bd)); t0 = fmaxf(t0, 0.f);
            float t1 = fmaf(w1, v1.y, fmaf(w0, v1.x, bd)); t1 = fmaxf(t1, 0.f);
            a0 = fmaf(v0.z, t0, a0);
            a1 = fmaf(v1.z, t1, a1);
        }
        g_upart[((size_t)b*8 + q*2 + half)*HID + d] = a0 + a1;
    }
}

// ---------------- K2b: speed, m, glo, mlp finish, folded-head output ----------------
__global__ void __launch_bounds__(1024)
k2b(const float* __restrict__ x,
    const float* __restrict__ Wg, const float* __restrict__ bgv,
    const float* __restrict__ Wm1, const float* __restrict__ bm1,
    const float* __restrict__ bm0,
    const float* __restrict__ Wp, const float* __restrict__ bp,
    float* __restrict__ out) {
    const int b = blockIdx.x;
    const int t = threadIdx.x;
    const int lane = t & 31, wid = t >> 5;

    __shared__ float red[32];
    __shared__ float sm[HID];
    __shared__ float m0[MLP_H], m1[MLP_H], glo8[OUTD];
    __shared__ float sgl[2];

    {
        const float* xp = x + (size_t)(b*NPTS + t)*FDIM;
        const float x3 = xp[3], x4 = xp[4];
        float sp = sqrtf(fmaf(x3, x3, x4*x4));
        #pragma unroll
        for (int s = 16; s > 0; s >>= 1) sp += __shfl_xor_sync(0xffffffffu, sp, s);
        if (lane == 0) red[wid] = sp;
    }
    if (t < HID) {
        float u = 0.f;
        #pragma unroll
        for (int c = 0; c < 8; c++) u += g_upart[((size_t)b*8 + c)*HID + t];
        sm[t] = u * (1.0f/1024.0f);
    } else if (t >= 512 && t < 512 + MLP_H) {
        const int h = t - 512;
        float a = bm0[h];
        #pragma unroll
        for (int s = 0; s < 7; s++) a += g_mlpPart[(b*7 + s)*MLP_H + h];
        m0[h] = fmaxf(a, 0.f);
    }
    __syncthreads();

    if (wid == 0) {
        float v = red[lane];
        #pragma unroll
        for (int s = 16; s > 0; s >>= 1) v += __shfl_xor_sync(0xffffffffu, v, s);
        if (lane == 0) {
            float mx = fmaxf(fmaxf(g_maxpart[b*4+0], g_maxpart[b*4+1]),
                             fmaxf(g_maxpart[b*4+2], g_maxpart[b*4+3]));
            sgl[0] = v * (1.0f/1024.0f);
            sgl[1] = 1.0f / sqrtf(mx);
        }
    }
    __syncthreads();

    if (t >= 768 && t < 768 + OUTD) {
        const int o = t - 768;
        const float ge = fmaf(Wg[2*o], sgl[0], fmaf(Wg[2*o + 1], sgl[1], bgv[o]));
        glo8[o] = fmaxf(ge, 0.f);
    }
    if (t < 256) {
        const int od = t >> 2, qq = t & 3;
        const float4* wr4 = (const float4*)(Wm1 + (size_t)od*MLP_H + qq*16);
        const float4* mm4 = (const float4*)(m0 + qq*16);
        float p = 0.f;
        #pragma unroll
        for (int e = 0; e < 4; e++) {
            const float4 wv = wr4[e], mv = mm4[e];
            p = fmaf(wv.x, mv.x, p); p = fmaf(wv.y, mv.y, p);
            p = fmaf(wv.z, mv.z, p); p = fmaf(wv.w, mv.w, p);
        }
        p += __shfl_xor_sync(0xffffffffu, p, 1);
        p += __shfl_xor_sync(0xffffffffu, p, 2);
        if (qq == 0) m1[od] = fmaxf(p + bm1[od], 0.f);
    }
    __syncthreads();

    if (wid < OUTD) {
        const int o = wid;
        const float* Eo = g_E + o*HID;
        const float* wp = Wp + (size_t)o*(MLP_H + HID + OUTD);
        float p = 0.f;
        #pragma unroll
        for (int c = 0; c < 8; c++)
            p = fmaf(Eo[c*32 + lane], sm[c*32 + lane], p);
        p = fmaf(wp[lane],      m1[lane],      p);
        p = fmaf(wp[32 + lane], m1[32 + lane], p);
        if (lane < OUTD) p = fmaf(wp[320 + lane], glo8[lane], p);
        #pragma unroll
        for (int s = 16; s > 0; s >>= 1) p += __shfl_xor_sync(0xffffffffu, p, s);
        if (lane == 0) out[b*OUTD + o] = p + bp[o] + g_c0[o];
    }
}

// ---------------- launch ----------------
extern "C" void kernel_launch(void* const* d_in, const int* in_sizes, int n_in,
                              void* d_out, int out_size) {
    (void)in_sizes; (void)n_in; (void)out_size;
    const float* x   = (const float*)d_in[0];
    const float* W1  = (const float*)d_in[1];
    const float* b1  = (const float*)d_in[2];
    const float* W2  = (const float*)d_in[3];
    const float* b2  = (const float*)d_in[4];
    const float* Wfc = (const float*)d_in[5];
    const float* bfc = (const float*)d_in[6];
    const float* Wg  = (const float*)d_in[7];
    const float* bg  = (const float*)d_in[8];
    const float* Wm0 = (const float*)d_in[9];
    const float* bm0 = (const float*)d_in[10];
    const float* Wm1 = (const float*)d_in[11];
    const float* bm1 = (const float*)d_in[12];
    const float* Wp  = (const float*)d_in[13];
    const float* bp  = (const float*)d_in[14];
    float* out = (float*)d_out;

    // smallest C with sqrtf(C) >= 0.3f  =>  (d2 < C) <=> (sqrtf(d2) < 0.3f)
    float C = 0.09f;
    while (sqrtf(C) >= 0.3f) C = nextafterf(C, 0.0f);
    while (sqrtf(C) <  0.3f) C = nextafterf(C, 1.0f);

    kA <<<192, 512>>>(x, Wm0, Wfc, W2, b2, bfc, Wp, C);
    k2a<<<dim3(4, BATCH), 512>>>(x, W1, b1);
    k2b<<<BATCH, 1024>>>(x, Wg, bg, Wm1, bm1, bm0, Wp, bp, out);
}